// round 15
// baseline (speedup 1.0000x reference)
#include <cuda_runtime.h>
#include <cuda_fp16.h>
#include <math.h>
#include <stdint.h>

#define SB   16
#define SS   2048
#define SD   128
#define BM   128
#define BN   64
#define NCH  64
#define CROWS 32

// scratch
__device__ float  g_SV[SB * SS * SD];     // suffix sums of V (exact fp32)
__device__ float  g_T[SB * NCH * SD];
__device__ __half g_Kh[SB * SS * SD];     // fp16 K, [b][kv][d]
__device__ __half g_Vt[SB * SS * SD];     // fp16 V TRANSPOSED, [b][d][kv]

// ---------------------------------------------------------------------------
__device__ __forceinline__ float ex2(float x) {
    float r; asm("ex2.approx.f32 %0, %1;" : "=f"(r) : "f"(x)); return r;
}
__device__ __forceinline__ unsigned h2u(__half2 h) {
    return *reinterpret_cast<unsigned*>(&h);
}
__device__ __forceinline__ void mma16(float c[4], unsigned a0, unsigned a1,
                                      unsigned a2, unsigned a3,
                                      unsigned b0, unsigned b1) {
    asm volatile(
        "mma.sync.aligned.m16n8k16.row.col.f32.f16.f16.f32 "
        "{%0,%1,%2,%3}, {%4,%5,%6,%7}, {%8,%9}, {%0,%1,%2,%3};"
        : "+f"(c[0]), "+f"(c[1]), "+f"(c[2]), "+f"(c[3])
        : "r"(a0), "r"(a1), "r"(a2), "r"(a3), "r"(b0), "r"(b1));
}
__device__ __forceinline__ void cp16(uint32_t dst, const void* src) {
    asm volatile("cp.async.cg.shared.global [%0], [%1], 16;" :: "r"(dst), "l"(src));
}
__device__ __forceinline__ void cp8(uint32_t dst, const void* src) {
    asm volatile("cp.async.ca.shared.global [%0], [%1], 8;" :: "r"(dst), "l"(src));
}

// ---------------------------------------------------------------------------
// Prologue A: K fp32 -> fp16 (rna), same [kv][d] layout
__global__ void kconv_kernel(const float4* __restrict__ K) {
    int i = blockIdx.x * 256 + threadIdx.x;
    float4 k = K[i];
    __half2* o = (__half2*)g_Kh;
    o[2 * i]     = __floats2half2_rn(k.x, k.y);
    o[2 * i + 1] = __floats2half2_rn(k.z, k.w);
}

// Prologue B: V -> fp16 transposed [b][d][kv], + 32-row chunk sums for SV
__global__ void vtrans_kernel(const float* __restrict__ V) {
    __shared__ float ts[64 * 129];
    int kvb = blockIdx.x, b = blockIdx.y;
    int tid = threadIdx.x;
    const float4* Vg = (const float4*)(V + ((size_t)b * SS + kvb * 64) * SD);
#pragma unroll
    for (int i = 0; i < 8; ++i) {
        int f = i * 256 + tid;
        int row = f >> 5, d4 = f & 31;
        float4 v = Vg[row * 32 + d4];
        float* p = ts + row * 129 + d4 * 4;
        p[0] = v.x; p[1] = v.y; p[2] = v.z; p[3] = v.w;
    }
    __syncthreads();
    uint2* Ot = (uint2*)g_Vt;
    // FIX (R13 bug): cover ALL 64 kv rows -> 2048 items: d = c>>4 (128), j = c&15 (16)
#pragma unroll
    for (int i = 0; i < 8; ++i) {
        int c = i * 256 + tid;
        int d = c >> 4, j = c & 15;
        float v0 = ts[(4 * j + 0) * 129 + d];
        float v1 = ts[(4 * j + 1) * 129 + d];
        float v2 = ts[(4 * j + 2) * 129 + d];
        float v3 = ts[(4 * j + 3) * 129 + d];
        __half2 h0 = __floats2half2_rn(v0, v1);
        __half2 h1 = __floats2half2_rn(v2, v3);
        Ot[((size_t)b * 128 + d) * 512 + kvb * 16 + j] = make_uint2(h2u(h0), h2u(h1));
    }
    // chunk sums (2 chunks of 32 kv rows per block)
    int d = tid & 127, hf = tid >> 7;
    float s = 0.f;
#pragma unroll
    for (int r = 0; r < 32; ++r) s += ts[(hf * 32 + r) * 129 + d];
    g_T[((size_t)b * NCH + kvb * 2 + hf) * SD + d] = s;
}

// Prologue C: suffix sums (exact fp32) for the masked-zeros correction
__global__ void suffix_kernel(const float* __restrict__ V) {
    int c = blockIdx.x, b = blockIdx.y, d = threadIdx.x;
    float acc = 0.f;
    for (int c2 = c + 1; c2 < NCH; ++c2) acc += g_T[(b * NCH + c2) * SD + d];
    const float* vp = V + ((b * SS + c * CROWS) * SD) + d;
    float*       sp = g_SV + ((b * SS + c * CROWS) * SD) + d;
#pragma unroll
    for (int k = CROWS - 1; k >= 0; --k) { sp[k * SD] = acc; acc += vp[k * SD]; }
}

// ---------------------------------------------------------------------------
// smem (bytes): K0[16K] V0[16K] K1[16K] V1[16K] = 64 KB
// K tile: 64 rows x 256B (row = permuted kv via chi), granule-swizz ^(2*(s&7))
// V tile: 128 rows x 128B (row = d),                granule-swizz ^(d&15)
#define OFF_K0 0
#define OFF_V0 16384
#define OFF_K1 32768
#define OFF_V1 49152
#define SMEM_BYTES 65536

__global__ __launch_bounds__(256, 1)
void flash_kernel(const float* __restrict__ Q, float* __restrict__ O) {
    extern __shared__ __align__(16) char smem[];
    const uint32_t sbase = (uint32_t)__cvta_generic_to_shared(smem);

    const int tid  = threadIdx.x;
    const int w    = tid >> 5;
    const int lane = tid & 31;
    const int g    = lane >> 2;      // 0..7
    const int m_   = lane & 3;       // 0..3
    const int b    = blockIdx.x;
    const int qtile = (gridDim.y - 1) - blockIdx.y;    // heavy-first
    const int R    = w * 16 + g;

    const float SCALE2 = 0.12751744f;   // log2(e)/sqrt(128), folded into Q

    const int nkt = 2 * qtile + 2;
    const __half* Kg_all = g_Kh + (size_t)b * SS * SD;     // [kv][d]
    const char*   Vt_all = (const char*)(g_Vt + (size_t)b * SS * SD);  // [d][kv]

    // ---- preload tile 0 ----
    {
        const char* Ks = (const char*)Kg_all;
#pragma unroll
        for (int i = 0; i < 4; ++i) {
            int f = i * 256 + tid;
            int kv = f >> 4, j = f & 15;
            // chi: kv = 16t+4m+2c+j  ->  s = 16t+8c+2m+j
            int s = ((kv >> 4) << 4) + (((kv >> 1) & 1) << 3) + (((kv >> 2) & 3) << 1) + (kv & 1);
            cp16(sbase + OFF_K0 + s * 256 + (((2 * j) ^ (2 * (s & 7))) << 3),
                 Ks + kv * 256 + j * 16);
        }
#pragma unroll
        for (int i = 0; i < 8; ++i) {
            int f = i * 256 + tid;
            int d = f >> 4, j = f & 15;
            cp8(sbase + OFF_V0 + d * 128 + ((j ^ (d & 15)) << 3),
                Vt_all + (size_t)d * 4096 + j * 8);
        }
        asm volatile("cp.async.commit_group;" ::: "memory");
    }

    // ---- Q fragments: prescaled fp16, d = 16ks + 4m_ .. +3 ----
    uint2 qa[2][8];
    {
        const float* Qr0 = Q + ((size_t)(b * SS) + qtile * BM + R) * SD + 4 * m_;
        const float* Qr1 = Qr0 + 8 * SD;
#pragma unroll
        for (int ks = 0; ks < 8; ++ks) {
            float4 q0 = *(const float4*)(Qr0 + 16 * ks);
            float4 q1 = *(const float4*)(Qr1 + 16 * ks);
            qa[0][ks] = make_uint2(h2u(__floats2half2_rn(q0.x * SCALE2, q0.y * SCALE2)),
                                   h2u(__floats2half2_rn(q0.z * SCALE2, q0.w * SCALE2)));
            qa[1][ks] = make_uint2(h2u(__floats2half2_rn(q1.x * SCALE2, q1.y * SCALE2)),
                                   h2u(__floats2half2_rn(q1.z * SCALE2, q1.w * SCALE2)));
        }
    }

    float l1 = 0.f, l2 = 0.f;
    // acc[nd] covers rows R,R+8 at d = 8*nd + 2m_, +1
    float acc[16][4];
#pragma unroll
    for (int nd = 0; nd < 16; ++nd)
#pragma unroll
        for (int e = 0; e < 4; ++e) acc[nd][e] = 0.f;

    for (int kt = 0; kt < nkt; ++kt) {
        const bool has_next = (kt + 1 < nkt);
        if (has_next) {
            const char* Ks = (const char*)(Kg_all + (size_t)(kt + 1) * BN * SD);
            const char* Vs = Vt_all + (size_t)(kt + 1) * 128;
            uint32_t kb = sbase + (((kt + 1) & 1) ? OFF_K1 : OFF_K0);
            uint32_t vb = sbase + (((kt + 1) & 1) ? OFF_V1 : OFF_V0);
#pragma unroll
            for (int i = 0; i < 4; ++i) {
                int f = i * 256 + tid;
                int kv = f >> 4, j = f & 15;
                int s = ((kv >> 4) << 4) + (((kv >> 1) & 1) << 3) + (((kv >> 2) & 3) << 1) + (kv & 1);
                cp16(kb + s * 256 + (((2 * j) ^ (2 * (s & 7))) << 3),
                     Ks + kv * 256 + j * 16);
            }
#pragma unroll
            for (int i = 0; i < 8; ++i) {
                int f = i * 256 + tid;
                int d = f >> 4, j = f & 15;
                cp8(vb + d * 128 + ((j ^ (d & 15)) << 3),
                    Vs + (size_t)d * 4096 + j * 8);
            }
            asm volatile("cp.async.commit_group;" ::: "memory");
            asm volatile("cp.async.wait_group 1;" ::: "memory");
        } else {
            asm volatile("cp.async.wait_group 0;" ::: "memory");
        }
        __syncthreads();   // tile kt visible

        // warps 0-3 (rows 0-63) fully masked on final kv tile: skip (exact)
        if (w >= 4 || kt != nkt - 1) {

        const char* Kb = smem + ((kt & 1) ? OFF_K1 : OFF_K0);
        const char* Vb = smem + ((kt & 1) ? OFF_V1 : OFF_V0);

        // ---- QK^T: one LDS.64 + one mma16 per (ks, nb) ----
        float sacc[8][4];
#pragma unroll
        for (int nb = 0; nb < 8; ++nb)
#pragma unroll
            for (int e = 0; e < 4; ++e) sacc[nb][e] = 0.f;

#pragma unroll
        for (int ks = 0; ks < 8; ++ks) {
            unsigned a0 = qa[0][ks].x, a1 = qa[1][ks].x;
            unsigned a2 = qa[0][ks].y, a3 = qa[1][ks].y;
            int xoff = ((4 * ks + m_) ^ (2 * g)) << 3;
#pragma unroll
            for (int nb = 0; nb < 8; ++nb) {
                uint2 bp = *(const uint2*)(Kb + (8 * nb + g) * 256 + xoff);
                mma16(sacc[nb], a0, a1, a2, a3, bp.x, bp.y);
            }
        }

        // ---- mask near the diagonal (permuted kv: gc = 64kt+16(nb>>1)+4m_+2(nb&1)) ----
        const int grow1 = qtile * BM + R;
        const int grow2 = grow1 + 8;
        if ((kt * BN + BN - 1) > (qtile * BM + w * 16)) {
#pragma unroll
            for (int nb = 0; nb < 8; ++nb) {
                int gc = kt * 64 + 16 * (nb >> 1) + 4 * m_ + 2 * (nb & 1);
                if (gc     > grow1) sacc[nb][0] = -1e30f;
                if (gc + 1 > grow1) sacc[nb][1] = -1e30f;
                if (gc     > grow2) sacc[nb][2] = -1e30f;
                if (gc + 1 > grow2) sacc[nb][3] = -1e30f;
            }
        }

        // ---- fixed-shift exp2 -> fp16 P (rna); l sums the ROUNDED values ----
        unsigned ph[8][2];
#pragma unroll
        for (int nb = 0; nb < 8; ++nb) {
            float r0 = ex2(sacc[nb][0]);
            float r1 = ex2(sacc[nb][1]);
            float r2 = ex2(sacc[nb][2]);
            float r3 = ex2(sacc[nb][3]);
            __half2 h0 = __floats2half2_rn(r0, r1);
            __half2 h1 = __floats2half2_rn(r2, r3);
            ph[nb][0] = h2u(h0); ph[nb][1] = h2u(h1);
            float2 f0 = __half22float2(h0); l1 += f0.x + f0.y;
            float2 f1 = __half22float2(h1); l2 += f1.x + f1.y;
        }

        // ---- P @ V: register P, one LDS.64 + one mma16 per (ks, nd) ----
#pragma unroll
        for (int ks = 0; ks < 4; ++ks) {
            unsigned a0 = ph[2 * ks][0],     a1 = ph[2 * ks][1];
            unsigned a2 = ph[2 * ks + 1][0], a3 = ph[2 * ks + 1][1];
            int xb = 4 * ks + m_;
#pragma unroll
            for (int nd = 0; nd < 16; ++nd) {
                int d = 8 * nd + g;
                uint2 bv = *(const uint2*)(Vb + d * 128 + ((xb ^ (d & 15)) << 3));
                mma16(acc[nd], a0, a1, a2, a3, bv.x, bv.y);
            }
        }

        }   // end active-warp skip
        __syncthreads();   // buffer free for refill
    }

    // ---- epilogue: reduce l, masked-zeros correction (shift 0), store ----
    l1 += __shfl_xor_sync(0xffffffffu, l1, 1);
    l1 += __shfl_xor_sync(0xffffffffu, l1, 2);
    l2 += __shfl_xor_sync(0xffffffffu, l2, 1);
    l2 += __shfl_xor_sync(0xffffffffu, l2, 2);

    const float2* SV2 = (const float2*)g_SV;
    float2*       O2  = (float2*)O;
#pragma unroll
    for (int h = 0; h < 2; ++h) {
        int grow = qtile * BM + R + 8 * h;
        float ll = h ? l2 : l1;
        long base = (long)(b * SS + grow) * 64;      // float2 units
        float cnt = (float)(SS - 1 - grow);
        if (cnt > 0.f) ll += cnt;                    // masked weights = exp2(0) = 1
        float inv = 1.0f / ll;
#pragma unroll
        for (int nd = 0; nd < 16; ++nd) {
            float o0 = acc[nd][2 * h + 0];
            float o1 = acc[nd][2 * h + 1];
            if (cnt > 0.f) {
                float2 sv = SV2[base + nd * 4 + m_];
                o0 += sv.x;
                o1 += sv.y;
            }
            O2[base + nd * 4 + m_] = make_float2(o0 * inv, o1 * inv);
        }
    }
}

// ---------------------------------------------------------------------------
extern "C" void kernel_launch(void* const* d_in, const int* in_sizes, int n_in,
                              void* d_out, int out_size) {
    const float* Q = (const float*)d_in[0];
    const float* K = (const float*)d_in[1];
    const float* V = (const float*)d_in[2];
    float*       O = (float*)d_out;

    cudaFuncSetAttribute(flash_kernel,
                         cudaFuncAttributeMaxDynamicSharedMemorySize, SMEM_BYTES);

    kconv_kernel <<<SB * SS * SD / 4 / 256, 256>>>((const float4*)K);
    vtrans_kernel<<<dim3(SS / 64, SB), 256>>>(V);
    suffix_kernel<<<dim3(NCH, SB), 128>>>(V);
    flash_kernel <<<dim3(SB, SS / BM), 256, SMEM_BYTES>>>(Q, O);
}

// round 16
// speedup vs baseline: 1.5953x; 1.5953x over previous
#include <cuda_runtime.h>
#include <cuda_fp16.h>
#include <math.h>
#include <stdint.h>

#define SB   16
#define SS   2048
#define SD   128
#define BM   128
#define BN   64
#define NCH  64
#define CROWS 32

// scratch
__device__ float  g_SV[SB * SS * SD];     // suffix sums of V (exact fp32)
__device__ float  g_T[SB * NCH * SD];
__device__ __half g_Kh[SB * SS * SD];     // fp16 K, [b][kv][d]
__device__ __half g_Vt[SB * SS * SD];     // fp16 V TRANSPOSED, [b][d][kv]

// ---------------------------------------------------------------------------
__device__ __forceinline__ float ex2(float x) {
    float r; asm("ex2.approx.f32 %0, %1;" : "=f"(r) : "f"(x)); return r;
}
__device__ __forceinline__ unsigned h2u(__half2 h) {
    return *reinterpret_cast<unsigned*>(&h);
}
__device__ __forceinline__ void mma16(float c[4], unsigned a0, unsigned a1,
                                      unsigned a2, unsigned a3,
                                      unsigned b0, unsigned b1) {
    asm volatile(
        "mma.sync.aligned.m16n8k16.row.col.f32.f16.f16.f32 "
        "{%0,%1,%2,%3}, {%4,%5,%6,%7}, {%8,%9}, {%0,%1,%2,%3};"
        : "+f"(c[0]), "+f"(c[1]), "+f"(c[2]), "+f"(c[3])
        : "r"(a0), "r"(a1), "r"(a2), "r"(a3), "r"(b0), "r"(b1));
}
__device__ __forceinline__ void cp16(uint32_t dst, const void* src) {
    asm volatile("cp.async.cg.shared.global [%0], [%1], 16;" :: "r"(dst), "l"(src));
}
__device__ __forceinline__ void cp8(uint32_t dst, const void* src) {
    asm volatile("cp.async.ca.shared.global [%0], [%1], 8;" :: "r"(dst), "l"(src));
}

// ---------------------------------------------------------------------------
// Prologue A: K fp32 -> fp16 (rna), same [kv][d] layout
__global__ void kconv_kernel(const float4* __restrict__ K) {
    int i = blockIdx.x * 256 + threadIdx.x;
    float4 k = K[i];
    __half2* o = (__half2*)g_Kh;
    o[2 * i]     = __floats2half2_rn(k.x, k.y);
    o[2 * i + 1] = __floats2half2_rn(k.z, k.w);
}

// Prologue B: V -> fp16 transposed [b][d][kv], + 32-row chunk sums for SV
__global__ void vtrans_kernel(const float* __restrict__ V) {
    __shared__ float ts[64 * 129];
    int kvb = blockIdx.x, b = blockIdx.y;
    int tid = threadIdx.x;
    const float4* Vg = (const float4*)(V + ((size_t)b * SS + kvb * 64) * SD);
#pragma unroll
    for (int i = 0; i < 8; ++i) {
        int f = i * 256 + tid;
        int row = f >> 5, d4 = f & 31;
        float4 v = Vg[row * 32 + d4];
        float* p = ts + row * 129 + d4 * 4;
        p[0] = v.x; p[1] = v.y; p[2] = v.z; p[3] = v.w;
    }
    __syncthreads();
    uint2* Ot = (uint2*)g_Vt;
#pragma unroll
    for (int i = 0; i < 8; ++i) {
        int c = i * 256 + tid;
        int d = c >> 4, j = c & 15;
        float v0 = ts[(4 * j + 0) * 129 + d];
        float v1 = ts[(4 * j + 1) * 129 + d];
        float v2 = ts[(4 * j + 2) * 129 + d];
        float v3 = ts[(4 * j + 3) * 129 + d];
        __half2 h0 = __floats2half2_rn(v0, v1);
        __half2 h1 = __floats2half2_rn(v2, v3);
        Ot[((size_t)b * 128 + d) * 512 + kvb * 16 + j] = make_uint2(h2u(h0), h2u(h1));
    }
    // chunk sums (2 chunks of 32 kv rows per block)
    int d = tid & 127, hf = tid >> 7;
    float s = 0.f;
#pragma unroll
    for (int r = 0; r < 32; ++r) s += ts[(hf * 32 + r) * 129 + d];
    g_T[((size_t)b * NCH + kvb * 2 + hf) * SD + d] = s;
}

// Prologue C: suffix sums (exact fp32) for the masked-zeros correction
__global__ void suffix_kernel(const float* __restrict__ V) {
    int c = blockIdx.x, b = blockIdx.y, d = threadIdx.x;
    float acc = 0.f;
    for (int c2 = c + 1; c2 < NCH; ++c2) acc += g_T[(b * NCH + c2) * SD + d];
    const float* vp = V + ((b * SS + c * CROWS) * SD) + d;
    float*       sp = g_SV + ((b * SS + c * CROWS) * SD) + d;
#pragma unroll
    for (int k = CROWS - 1; k >= 0; --k) { sp[k * SD] = acc; acc += vp[k * SD]; }
}

// ---------------------------------------------------------------------------
// smem (bytes): K0[16K] V0[16K] K1[16K] V1[16K] = 64 KB
// K tile: 64 rows x 256B (row = chi-permuted kv); granule j at j^((s&3)<<1)
// V tile: 128 rows x 128B (row = d);              octet  j at j^((d&3)<<2)
// Bank-pair keys put g in bits 2-3 (disjoint from m_ in bits 0-1): conflict-free.
#define OFF_K0 0
#define OFF_V0 16384
#define OFF_K1 32768
#define OFF_V1 49152
#define SMEM_BYTES 65536

__global__ __launch_bounds__(256, 1)
void flash_kernel(const float* __restrict__ Q, float* __restrict__ O) {
    extern __shared__ __align__(16) char smem[];
    const uint32_t sbase = (uint32_t)__cvta_generic_to_shared(smem);

    const int tid  = threadIdx.x;
    const int w    = tid >> 5;
    const int lane = tid & 31;
    const int g    = lane >> 2;      // 0..7
    const int m_   = lane & 3;       // 0..3
    const int b    = blockIdx.x;
    const int qtile = (gridDim.y - 1) - blockIdx.y;    // heavy-first
    const int R    = w * 16 + g;

    const float SCALE2 = 0.12751744f;   // log2(e)/sqrt(128), folded into Q

    const int nkt = 2 * qtile + 2;
    const __half* Kg_all = g_Kh + (size_t)b * SS * SD;     // [kv][d]
    const char*   Vt_all = (const char*)(g_Vt + (size_t)b * SS * SD);  // [d][kv]

    // ---- preload tile 0 ----
    {
        const char* Ks = (const char*)Kg_all;
#pragma unroll
        for (int i = 0; i < 4; ++i) {
            int f = i * 256 + tid;
            int kv = f >> 4, j = f & 15;
            // chi: kv = 16t+4m+2c+j  ->  s = 16t+8c+2m+j
            int s = ((kv >> 4) << 4) + (((kv >> 1) & 1) << 3) + (((kv >> 2) & 3) << 1) + (kv & 1);
            cp16(sbase + OFF_K0 + s * 256 + ((j ^ ((s & 3) << 1)) << 4),
                 Ks + kv * 256 + j * 16);
        }
#pragma unroll
        for (int i = 0; i < 8; ++i) {
            int f = i * 256 + tid;
            int d = f >> 4, j = f & 15;
            cp8(sbase + OFF_V0 + d * 128 + ((j ^ ((d & 3) << 2)) << 3),
                Vt_all + (size_t)d * 4096 + j * 8);
        }
        asm volatile("cp.async.commit_group;" ::: "memory");
    }

    // ---- Q fragments: prescaled fp16, d = 16ks + 4m_ .. +3 ----
    uint2 qa[2][8];
    {
        const float* Qr0 = Q + ((size_t)(b * SS) + qtile * BM + R) * SD + 4 * m_;
        const float* Qr1 = Qr0 + 8 * SD;
#pragma unroll
        for (int ks = 0; ks < 8; ++ks) {
            float4 q0 = *(const float4*)(Qr0 + 16 * ks);
            float4 q1 = *(const float4*)(Qr1 + 16 * ks);
            qa[0][ks] = make_uint2(h2u(__floats2half2_rn(q0.x * SCALE2, q0.y * SCALE2)),
                                   h2u(__floats2half2_rn(q0.z * SCALE2, q0.w * SCALE2)));
            qa[1][ks] = make_uint2(h2u(__floats2half2_rn(q1.x * SCALE2, q1.y * SCALE2)),
                                   h2u(__floats2half2_rn(q1.z * SCALE2, q1.w * SCALE2)));
        }
    }

    float l1 = 0.f, l2 = 0.f;
    // acc[nd] covers rows R,R+8 at d = 8*nd + 2m_, +1
    float acc[16][4];
#pragma unroll
    for (int nd = 0; nd < 16; ++nd)
#pragma unroll
        for (int e = 0; e < 4; ++e) acc[nd][e] = 0.f;

    const int gkey = (g & 3) << 2;   // swizzle read key (bits 2-3)

    for (int kt = 0; kt < nkt; ++kt) {
        const bool has_next = (kt + 1 < nkt);
        if (has_next) {
            const char* Ks = (const char*)(Kg_all + (size_t)(kt + 1) * BN * SD);
            const char* Vs = Vt_all + (size_t)(kt + 1) * 128;
            uint32_t kb = sbase + (((kt + 1) & 1) ? OFF_K1 : OFF_K0);
            uint32_t vb = sbase + (((kt + 1) & 1) ? OFF_V1 : OFF_V0);
#pragma unroll
            for (int i = 0; i < 4; ++i) {
                int f = i * 256 + tid;
                int kv = f >> 4, j = f & 15;
                int s = ((kv >> 4) << 4) + (((kv >> 1) & 1) << 3) + (((kv >> 2) & 3) << 1) + (kv & 1);
                cp16(kb + s * 256 + ((j ^ ((s & 3) << 1)) << 4),
                     Ks + kv * 256 + j * 16);
            }
#pragma unroll
            for (int i = 0; i < 8; ++i) {
                int f = i * 256 + tid;
                int d = f >> 4, j = f & 15;
                cp8(vb + d * 128 + ((j ^ ((d & 3) << 2)) << 3),
                    Vs + (size_t)d * 4096 + j * 8);
            }
            asm volatile("cp.async.commit_group;" ::: "memory");
            asm volatile("cp.async.wait_group 1;" ::: "memory");
        } else {
            asm volatile("cp.async.wait_group 0;" ::: "memory");
        }
        __syncthreads();   // tile kt visible

        // warps 0-3 (rows 0-63) fully masked on final kv tile: skip (exact)
        if (w >= 4 || kt != nkt - 1) {

        const char* Kb = smem + ((kt & 1) ? OFF_K1 : OFF_K0);
        const char* Vb = smem + ((kt & 1) ? OFF_V1 : OFF_V0);

        // ---- QK^T: one LDS.64 + one mma16 per (ks, nb); row&3 == g&3 ----
        float sacc[8][4];
#pragma unroll
        for (int nb = 0; nb < 8; ++nb)
#pragma unroll
            for (int e = 0; e < 4; ++e) sacc[nb][e] = 0.f;

#pragma unroll
        for (int ks = 0; ks < 8; ++ks) {
            unsigned a0 = qa[0][ks].x, a1 = qa[1][ks].x;
            unsigned a2 = qa[0][ks].y, a3 = qa[1][ks].y;
            int xoff = ((4 * ks + m_) ^ gkey) << 3;
#pragma unroll
            for (int nb = 0; nb < 8; ++nb) {
                uint2 bp = *(const uint2*)(Kb + (8 * nb + g) * 256 + xoff);
                mma16(sacc[nb], a0, a1, a2, a3, bp.x, bp.y);
            }
        }

        // ---- mask near the diagonal (permuted kv: gc = 64kt+16(nb>>1)+4m_+2(nb&1)) ----
        const int grow1 = qtile * BM + R;
        const int grow2 = grow1 + 8;
        if ((kt * BN + BN - 1) > (qtile * BM + w * 16)) {
#pragma unroll
            for (int nb = 0; nb < 8; ++nb) {
                int gc = kt * 64 + 16 * (nb >> 1) + 4 * m_ + 2 * (nb & 1);
                if (gc     > grow1) sacc[nb][0] = -1e30f;
                if (gc + 1 > grow1) sacc[nb][1] = -1e30f;
                if (gc     > grow2) sacc[nb][2] = -1e30f;
                if (gc + 1 > grow2) sacc[nb][3] = -1e30f;
            }
        }

        // ---- fixed-shift exp2 -> fp16 P (rna); l sums the ROUNDED values ----
        unsigned ph[8][2];
#pragma unroll
        for (int nb = 0; nb < 8; ++nb) {
            float r0 = ex2(sacc[nb][0]);
            float r1 = ex2(sacc[nb][1]);
            float r2 = ex2(sacc[nb][2]);
            float r3 = ex2(sacc[nb][3]);
            __half2 h0 = __floats2half2_rn(r0, r1);
            __half2 h1 = __floats2half2_rn(r2, r3);
            ph[nb][0] = h2u(h0); ph[nb][1] = h2u(h1);
            float2 f0 = __half22float2(h0); l1 += f0.x + f0.y;
            float2 f1 = __half22float2(h1); l2 += f1.x + f1.y;
        }

        // ---- P @ V: register P, one LDS.64 + one mma16 per (ks, nd); d&3 == g&3 ----
#pragma unroll
        for (int ks = 0; ks < 4; ++ks) {
            unsigned a0 = ph[2 * ks][0],     a1 = ph[2 * ks][1];
            unsigned a2 = ph[2 * ks + 1][0], a3 = ph[2 * ks + 1][1];
            int voff = ((4 * ks + m_) ^ gkey) << 3;
#pragma unroll
            for (int nd = 0; nd < 16; ++nd) {
                uint2 bv = *(const uint2*)(Vb + (8 * nd + g) * 128 + voff);
                mma16(acc[nd], a0, a1, a2, a3, bv.x, bv.y);
            }
        }

        }   // end active-warp skip
        __syncthreads();   // buffer free for refill
    }

    // ---- epilogue: reduce l, masked-zeros correction (shift 0), store ----
    l1 += __shfl_xor_sync(0xffffffffu, l1, 1);
    l1 += __shfl_xor_sync(0xffffffffu, l1, 2);
    l2 += __shfl_xor_sync(0xffffffffu, l2, 1);
    l2 += __shfl_xor_sync(0xffffffffu, l2, 2);

    const float2* SV2 = (const float2*)g_SV;
    float2*       O2  = (float2*)O;
#pragma unroll
    for (int h = 0; h < 2; ++h) {
        int grow = qtile * BM + R + 8 * h;
        float ll = h ? l2 : l1;
        long base = (long)(b * SS + grow) * 64;      // float2 units
        float cnt = (float)(SS - 1 - grow);
        if (cnt > 0.f) ll += cnt;                    // masked weights = exp2(0) = 1
        float inv = 1.0f / ll;
#pragma unroll
        for (int nd = 0; nd < 16; ++nd) {
            float o0 = acc[nd][2 * h + 0];
            float o1 = acc[nd][2 * h + 1];
            if (cnt > 0.f) {
                float2 sv = SV2[base + nd * 4 + m_];
                o0 += sv.x;
                o1 += sv.y;
            }
            O2[base + nd * 4 + m_] = make_float2(o0 * inv, o1 * inv);
        }
    }
}

// ---------------------------------------------------------------------------
extern "C" void kernel_launch(void* const* d_in, const int* in_sizes, int n_in,
                              void* d_out, int out_size) {
    const float* Q = (const float*)d_in[0];
    const float* K = (const float*)d_in[1];
    const float* V = (const float*)d_in[2];
    float*       O = (float*)d_out;

    cudaFuncSetAttribute(flash_kernel,
                         cudaFuncAttributeMaxDynamicSharedMemorySize, SMEM_BYTES);

    kconv_kernel <<<SB * SS * SD / 4 / 256, 256>>>((const float4*)K);
    vtrans_kernel<<<dim3(SS / 64, SB), 256>>>(V);
    suffix_kernel<<<dim3(NCH, SB), 128>>>(V);
    flash_kernel <<<dim3(SB, SS / BM), 256, SMEM_BYTES>>>(Q, O);
}